// round 8
// baseline (speedup 1.0000x reference)
#include <cuda_runtime.h>
#include <cstdint>
#include <cstddef>

#define SQ 4096
#define NB 64
#define HH 256
#define GC 1024   // 4 gates * 256 units, packed: pcol = j*4 + e  (e: 0=f,1=i,2=o,3=c)

#define CANARY 0x7FBADBADu   // NaN payload; h = sig*tanh can never be NaN

typedef unsigned long long ull;

// ---------------- static device scratch (no allocations allowed) ----------------
__device__ float g_xg[(size_t)SQ * NB * GC];     // 1 GB input projections (+bias)
__device__ float g_Wp[HH * GC];                  // packed W_all [k][pcol]
__device__ float g_Up[HH * GC];                  // packed U_all [k][pcol]
__device__ float g_bp[GC];                       // packed bias
__device__ float g_hT[NB * HH];                  // final hidden state
__device__ unsigned g_hx[2][4][16][2][HH];       // h ring [pair][buf][grp][b][k], 256KB

// ---------------- f32x2 helpers ----------------
__device__ __forceinline__ ull pk2(float x, float y) {
    ull r; asm("mov.b64 %0, {%1, %2};" : "=l"(r) : "f"(x), "f"(y)); return r;
}
__device__ __forceinline__ void fma2(ull& d, ull a, ull b) {
    asm("fma.rn.f32x2 %0, %1, %2, %0;" : "+l"(d) : "l"(a), "l"(b));
}
__device__ __forceinline__ float2 unpk(ull v) {
    float2 r; asm("mov.b64 {%0, %1}, %2;" : "=f"(r.x), "=f"(r.y) : "l"(v)); return r;
}
union F4U2 { float4 f4; ulonglong2 u2; };

__device__ __forceinline__ unsigned ldacq(const unsigned* p) {
    unsigned v; asm volatile("ld.acquire.gpu.u32 %0, [%1];" : "=r"(v) : "l"(p) : "memory"); return v;
}
__device__ __forceinline__ void strel(unsigned* p, unsigned v) {
    asm volatile("st.release.gpu.u32 [%0], %1;" :: "l"(p), "r"(v) : "memory");
}
__device__ __forceinline__ float fsig(float x) {   // 1/(1+e^-x) via fast exp
    return 1.0f / (1.0f + __expf(-x));
}
__device__ __forceinline__ float ftanh(float x) {  // 1 - 2/(e^2x+1)
    return 1.0f - 2.0f / (__expf(2.0f * x) + 1.0f);
}

// ---------------- phase 0: pack weights + poison exchange ring ----------------
__global__ void pack_kernel(const float* __restrict__ Wf, const float* __restrict__ Uf, const float* __restrict__ bf,
                            const float* __restrict__ Wi, const float* __restrict__ Ui, const float* __restrict__ bi,
                            const float* __restrict__ Wc, const float* __restrict__ Uc, const float* __restrict__ bc,
                            const float* __restrict__ Wo, const float* __restrict__ Uo, const float* __restrict__ bo)
{
    int i = blockIdx.x * blockDim.x + threadIdx.x;   // 0 .. 262143
    if (i < HH * GC) {
        int k = i >> 10, p = i & 1023;
        int j = p >> 2, e = p & 3;                   // e: 0=f,1=i,2=o,3=c
        const float* W = (e == 0) ? Wf : (e == 1) ? Wi : (e == 2) ? Wo : Wc;
        const float* U = (e == 0) ? Uf : (e == 1) ? Ui : (e == 2) ? Uo : Uc;
        g_Wp[i] = W[k * HH + j];
        g_Up[i] = U[k * HH + j];
        if (k == 0) {
            const float* B = (e == 0) ? bf : (e == 1) ? bi : (e == 2) ? bo : bc;
            g_bp[p] = B[j];
        }
    }
    if (i < 2 * 4 * 16 * 2 * HH) ((unsigned*)g_hx)[i] = CANARY;
}

// ---------------- phase 1: xg[s*64+b][pcol] = x[b][s][:] @ Wp + bias ----------------
__global__ __launch_bounds__(256) void xproj_kernel(const float* __restrict__ x)
{
    __shared__ float As[8][132];   // [k][m], padded
    __shared__ float Bs[8][128];   // [k][n]
    int t  = threadIdx.x;
    int m0 = blockIdx.x * 128;
    int n0 = blockIdx.y * 128;
    int tm = t >> 4, tn = t & 15;

    int arow = t >> 1;
    int akq  = (t & 1) * 4;
    int gm = m0 + arow;
    int bb = gm & 63, ss = gm >> 6;
    const float* aptr = x + ((size_t)bb * SQ + ss) * HH + akq;

    int bkk = t >> 5;
    int bnq = (t & 31) * 4;
    const float* bptr = g_Wp + (size_t)bkk * GC + n0 + bnq;

    ull acc[8][4];
#pragma unroll
    for (int i = 0; i < 8; i++)
#pragma unroll
        for (int j = 0; j < 4; j++) acc[i][j] = 0ull;

    for (int k0 = 0; k0 < HH; k0 += 8) {
        float4 av = *(const float4*)(aptr + k0);
        float4 bv = *(const float4*)(bptr + (size_t)k0 * GC);
        __syncthreads();
        As[akq + 0][arow] = av.x;
        As[akq + 1][arow] = av.y;
        As[akq + 2][arow] = av.z;
        As[akq + 3][arow] = av.w;
        *(float4*)&Bs[bkk][bnq] = bv;
        __syncthreads();
#pragma unroll
        for (int kk = 0; kk < 8; kk++) {
            F4U2 b0, b1;
            float4 a0 = *(const float4*)&As[kk][tm * 8];
            float4 a1 = *(const float4*)&As[kk][tm * 8 + 4];
            b0.f4 = *(const float4*)&Bs[kk][tn * 8];
            b1.f4 = *(const float4*)&Bs[kk][tn * 8 + 4];
            ull bp_[4] = { b0.u2.x, b0.u2.y, b1.u2.x, b1.u2.y };
            float aa[8] = { a0.x, a0.y, a0.z, a0.w, a1.x, a1.y, a1.z, a1.w };
#pragma unroll
            for (int i = 0; i < 8; i++) {
                ull ad = pk2(aa[i], aa[i]);
#pragma unroll
                for (int j = 0; j < 4; j++) fma2(acc[i][j], ad, bp_[j]);
            }
        }
    }

    float4 bi0 = *(const float4*)(g_bp + n0 + tn * 8);
    float4 bi1 = *(const float4*)(g_bp + n0 + tn * 8 + 4);
#pragma unroll
    for (int i = 0; i < 8; i++) {
        float2 v0 = unpk(acc[i][0]), v1 = unpk(acc[i][1]);
        float2 v2 = unpk(acc[i][2]), v3 = unpk(acc[i][3]);
        float* o = g_xg + (size_t)(m0 + tm * 8 + i) * GC + n0 + tn * 8;
        float4 w0 = { v0.x + bi0.x, v0.y + bi0.y, v1.x + bi0.z, v1.y + bi0.w };
        float4 w1 = { v2.x + bi1.x, v2.y + bi1.y, v3.x + bi1.z, v3.y + bi1.w };
        *(float4*)o = w0;
        *(float4*)(o + 4) = w1;
    }
}

// ---------------- phase 2: persistent recurrence, batch-pair pipelined ----------------
// 128 CTAs = 16 groups x 8 col-CTAs. Group's 4 batches split into pair A={0,1},
// B={2,3}; halves interleave so each pair's h L2-round-trip hides behind the other
// pair's GEMM. Canary-poll exchange (polls expected to hit first try).
__global__ __launch_bounds__(256, 1) void rnn_kernel()
{
    extern __shared__ float smU[];        // [8 ks][16 rows (kk=16..31)][128 cols] = 64KB
    __shared__ ull  smH[2][HH * 2];       // [pair][k*2 + b] duplicated pairs, 2x4KB
    __shared__ float smR[8][2][128];      // [ksplit][b][col] 8KB

    int t   = threadIdx.x;
    int grp = blockIdx.x >> 3;
    int r   = blockIdx.x & 7;
    int c0  = r * 128;
    int gb  = grp * 4;

    int ks = t >> 5;                 // 8 k-splits of 32
    int cg = t & 31;                 // col quad within CTA slice
    int rb = (t >> 5) & 1;           // epilogue (t<64): batch-in-pair
    int ru = t & 31;                 // epilogue: unit idx within slice

    // smU: rows kk=16..31 of each split
    {
        float4* dst = (float4*)smU;
        for (int q = t; q < 128 * 32; q += 256) {
            int row = q >> 5, cq4 = q & 31;
            int ks2 = row >> 4, j = row & 15;
            int kg = ks2 * 32 + 16 + j;
            dst[q] = *(const float4*)(g_Up + (size_t)kg * GC + c0 + cq4 * 4);
        }
    }
    // register half: rows kk=0..15 of this thread's split (pre-packed col pairs)
    ull ur0[16], ur1[16];
#pragma unroll
    for (int kk = 0; kk < 16; kk++) {
        int kg = ks * 32 + kk;
        F4U2 v; v.f4 = __ldg((const float4*)(g_Up + (size_t)kg * GC + c0 + 4 * cg));
        ur0[kk] = v.u2.x;
        ur1[kk] = v.u2.y;
    }
    // step 0 consumes h = 0 for both pairs
    for (int i = t; i < 2 * HH * 2; i += 256) ((ull*)smH)[i] = 0ull;

    float C0 = 0.0f, C1 = 0.0f;      // cell state for half A / half B (t<64)
    int unit = r * 32 + ru;

    for (int s = 0; s < SQ; s++) {
        // prefetch xg for both halves before any polling
        float4 xgA, xgB;
        if (t < 64) {
            const float* base = g_xg + ((size_t)s * NB + gb) * GC + c0 + 4 * ru;
            xgA = __ldcs((const float4*)(base + (size_t)rb * GC));
            xgB = __ldcs((const float4*)(base + (size_t)(rb + 2) * GC));
        }

        // ---------------- half A ----------------
        if (s > 0) {
            const unsigned* sl = &g_hx[0][s & 3][grp][0][t];
            unsigned v0, v1;
            do { v0 = ldacq(sl); v1 = ldacq(sl + HH); } while (v0 == CANARY || v1 == CANARY);
            float h0 = __uint_as_float(v0), h1 = __uint_as_float(v1);
            ulonglong2 pr; pr.x = pk2(h0, h0); pr.y = pk2(h1, h1);
            *(ulonglong2*)&smH[0][t * 2] = pr;
        }
        __syncthreads();
        {
            ull a00 = 0, a01 = 0, a10 = 0, a11 = 0;
            const ull* H = smH[0];
            int kb = ks * 32;
#pragma unroll
            for (int kk = 0; kk < 16; kk++) {
                ulonglong2 h = *(const ulonglong2*)&H[(kb + kk) * 2];
                fma2(a00, h.x, ur0[kk]); fma2(a01, h.x, ur1[kk]);
                fma2(a10, h.y, ur0[kk]); fma2(a11, h.y, ur1[kk]);
            }
#pragma unroll
            for (int kk = 0; kk < 16; kk++) {
                F4U2 u; u.f4 = *(const float4*)&smU[(ks * 16 + kk) * 128 + 4 * cg];
                ulonglong2 h = *(const ulonglong2*)&H[(kb + 16 + kk) * 2];
                fma2(a00, h.x, u.u2.x); fma2(a01, h.x, u.u2.y);
                fma2(a10, h.y, u.u2.x); fma2(a11, h.y, u.u2.y);
            }
            float2 x0 = unpk(a00), x1 = unpk(a01);
            *(float4*)&smR[ks][0][4 * cg] = make_float4(x0.x, x0.y, x1.x, x1.y);
            x0 = unpk(a10); x1 = unpk(a11);
            *(float4*)&smR[ks][1][4 * cg] = make_float4(x0.x, x0.y, x1.x, x1.y);
        }
        __syncthreads();
        if (t < 64) {
            float4 g4 = xgA;
#pragma unroll
            for (int q = 0; q < 8; q++) {
                float4 pv = *(const float4*)&smR[q][rb][4 * ru];
                g4.x += pv.x; g4.y += pv.y; g4.z += pv.z; g4.w += pv.w;
            }
            float fg = fsig(g4.x), ig = fsig(g4.y), og = fsig(g4.z), cc = fsig(g4.w);
            C0 = fg * C0 + ig * cc;
            float h = og * ftanh(C0);
            if (s < SQ - 1) {
                g_hx[0][(s + 2) & 3][grp][rb][unit] = CANARY;           // re-poison 2 ahead
                strel(&g_hx[0][(s + 1) & 3][grp][rb][unit], __float_as_uint(h));
            } else {
                g_hT[(gb + rb) * HH + unit] = h;
            }
        }

        // ---------------- half B ----------------
        if (s > 0) {
            const unsigned* sl = &g_hx[1][s & 3][grp][0][t];
            unsigned v0, v1;
            do { v0 = ldacq(sl); v1 = ldacq(sl + HH); } while (v0 == CANARY || v1 == CANARY);
            float h0 = __uint_as_float(v0), h1 = __uint_as_float(v1);
            ulonglong2 pr; pr.x = pk2(h0, h0); pr.y = pk2(h1, h1);
            *(ulonglong2*)&smH[1][t * 2] = pr;
        }
        __syncthreads();
        {
            ull a00 = 0, a01 = 0, a10 = 0, a11 = 0;
            const ull* H = smH[1];
            int kb = ks * 32;
#pragma unroll
            for (int kk = 0; kk < 16; kk++) {
                ulonglong2 h = *(const ulonglong2*)&H[(kb + kk) * 2];
                fma2(a00, h.x, ur0[kk]); fma2(a01, h.x, ur1[kk]);
                fma2(a10, h.y, ur0[kk]); fma2(a11, h.y, ur1[kk]);
            }
#pragma unroll
            for (int kk = 0; kk < 16; kk++) {
                F4U2 u; u.f4 = *(const float4*)&smU[(ks * 16 + kk) * 128 + 4 * cg];
                ulonglong2 h = *(const ulonglong2*)&H[(kb + 16 + kk) * 2];
                fma2(a00, h.x, u.u2.x); fma2(a01, h.x, u.u2.y);
                fma2(a10, h.y, u.u2.x); fma2(a11, h.y, u.u2.y);
            }
            float2 x0 = unpk(a00), x1 = unpk(a01);
            *(float4*)&smR[ks][0][4 * cg] = make_float4(x0.x, x0.y, x1.x, x1.y);
            x0 = unpk(a10); x1 = unpk(a11);
            *(float4*)&smR[ks][1][4 * cg] = make_float4(x0.x, x0.y, x1.x, x1.y);
        }
        __syncthreads();
        if (t < 64) {
            float4 g4 = xgB;
#pragma unroll
            for (int q = 0; q < 8; q++) {
                float4 pv = *(const float4*)&smR[q][rb][4 * ru];
                g4.x += pv.x; g4.y += pv.y; g4.z += pv.z; g4.w += pv.w;
            }
            float fg = fsig(g4.x), ig = fsig(g4.y), og = fsig(g4.z), cc = fsig(g4.w);
            C1 = fg * C1 + ig * cc;
            float h = og * ftanh(C1);
            if (s < SQ - 1) {
                g_hx[1][(s + 2) & 3][grp][rb][unit] = CANARY;
                strel(&g_hx[1][(s + 1) & 3][grp][rb][unit], __float_as_uint(h));
            } else {
                g_hT[(gb + 2 + rb) * HH + unit] = h;
            }
        }
    }
}

// ---------------- phase 3: out = h_T @ Why + bias_y ----------------
__global__ __launch_bounds__(256) void out_kernel(const float* __restrict__ Why,
                                                  const float* __restrict__ by,
                                                  float* __restrict__ out)
{
    __shared__ float hs[HH];
    int b = blockIdx.x, n = threadIdx.x;
    hs[n] = g_hT[b * HH + n];
    __syncthreads();
    float acc = by[n];
    for (int k = 0; k < HH; k++)
        acc = fmaf(hs[k], Why[(size_t)k * HH + n], acc);
    out[b * HH + n] = acc;
}

// ---------------- launch ----------------
extern "C" void kernel_launch(void* const* d_in, const int* in_sizes, int n_in,
                              void* d_out, int out_size)
{
    (void)in_sizes; (void)n_in; (void)out_size;
    const float* x   = (const float*)d_in[0];
    const float* Wf  = (const float*)d_in[1];
    const float* Uf  = (const float*)d_in[2];
    const float* bf  = (const float*)d_in[3];
    const float* Wi  = (const float*)d_in[4];
    const float* Ui  = (const float*)d_in[5];
    const float* bi  = (const float*)d_in[6];
    const float* Wc  = (const float*)d_in[7];
    const float* Uc  = (const float*)d_in[8];
    const float* bc  = (const float*)d_in[9];
    const float* Wo  = (const float*)d_in[10];
    const float* Uo  = (const float*)d_in[11];
    const float* bo  = (const float*)d_in[12];
    const float* Why = (const float*)d_in[13];
    const float* by  = (const float*)d_in[14];
    float* out = (float*)d_out;

    pack_kernel<<<1024, 256>>>(Wf, Uf, bf, Wi, Ui, bi, Wc, Uc, bc, Wo, Uo, bo);

    dim3 g1(2048, 8);
    xproj_kernel<<<g1, 256>>>(x);

    int smem = 128 * 128 * (int)sizeof(float);   // 64KB dynamic (smU)
    cudaFuncSetAttribute(rnn_kernel, cudaFuncAttributeMaxDynamicSharedMemorySize, smem);
    rnn_kernel<<<128, 256, smem>>>();

    out_kernel<<<64, 256>>>(Why, by, out);
}

// round 9
// speedup vs baseline: 1.6633x; 1.6633x over previous
#include <cuda_runtime.h>
#include <cstdint>
#include <cstddef>

#define SQ 4096
#define NB 64
#define HH 256
#define GC 1024   // 4 gates * 256 units, packed: pcol = j*4 + e  (e: 0=f,1=i,2=o,3=c)

typedef unsigned long long ull;

// ---------------- static device scratch (no allocations allowed) ----------------
__device__ float g_xg[(size_t)SQ * NB * GC];   // 1 GB input projections (+bias)
__device__ float g_Wp[HH * GC];                // packed W_all [k][pcol]
__device__ float g_Up[HH * GC];                // packed U_all [k][pcol]
__device__ float g_bp[GC];                     // packed bias
__device__ float g_hT[NB * HH];                // final hidden state
__device__ ull      g_mb[4][16][HH][4];        // mailbox ring: duplicated h pairs [buf][grp][k][b]
__device__ unsigned g_fl[16][8][32];           // per-(grp, producer CTA) flags, 128B padded

// ---------------- f32x2 + memory helpers ----------------
__device__ __forceinline__ ull pk2(float x, float y) {
    ull r; asm("mov.b64 %0, {%1, %2};" : "=l"(r) : "f"(x), "f"(y)); return r;
}
__device__ __forceinline__ void fma2(ull& d, ull a, ull b) {
    asm("fma.rn.f32x2 %0, %1, %2, %0;" : "+l"(d) : "l"(a), "l"(b));
}
__device__ __forceinline__ float2 unpk(ull v) {
    float2 r; asm("mov.b64 {%0, %1}, %2;" : "=f"(r.x), "=f"(r.y) : "l"(v)); return r;
}
union F4U2 { float4 f4; ulonglong2 u2; };

__device__ __forceinline__ unsigned ldacq(const unsigned* p) {
    unsigned v; asm volatile("ld.acquire.gpu.global.u32 %0, [%1];" : "=r"(v) : "l"(p) : "memory"); return v;
}
__device__ __forceinline__ void strel64(ull* p, ull v) {
    asm volatile("st.relaxed.gpu.global.u64 [%0], %1;" :: "l"(p), "l"(v) : "memory");
}
__device__ __forceinline__ void redrel(unsigned* p) {
    asm volatile("red.release.gpu.global.add.u32 [%0], 1;" :: "l"(p) : "memory");
}
__device__ __forceinline__ float fsig(float x) { return 1.0f / (1.0f + __expf(-x)); }
__device__ __forceinline__ float ftanh(float x) { return 1.0f - 2.0f / (__expf(2.0f * x) + 1.0f); }

// ---------------- phase 0: pack weights + init mailbox/flags ----------------
__global__ void pack_kernel(const float* __restrict__ Wf, const float* __restrict__ Uf, const float* __restrict__ bf,
                            const float* __restrict__ Wi, const float* __restrict__ Ui, const float* __restrict__ bi,
                            const float* __restrict__ Wc, const float* __restrict__ Uc, const float* __restrict__ bc,
                            const float* __restrict__ Wo, const float* __restrict__ Uo, const float* __restrict__ bo)
{
    int i = blockIdx.x * blockDim.x + threadIdx.x;   // 0 .. 262143
    if (i < HH * GC) {
        int k = i >> 10, p = i & 1023;
        int j = p >> 2, e = p & 3;                   // e: 0=f,1=i,2=o,3=c
        const float* W = (e == 0) ? Wf : (e == 1) ? Wi : (e == 2) ? Wo : Wc;
        const float* U = (e == 0) ? Uf : (e == 1) ? Ui : (e == 2) ? Uo : Uc;
        g_Wp[i] = W[k * HH + j];
        g_Up[i] = U[k * HH + j];
        if (k == 0) {
            const float* B = (e == 0) ? bf : (e == 1) ? bi : (e == 2) ? bo : bc;
            g_bp[p] = B[j];
        }
    }
    if (i < 16 * HH * 4) ((ull*)g_mb)[i] = 0ull;        // buf 0 = zeros (step-0 h)
    if (i < 16 * 8 * 32) ((unsigned*)g_fl)[i] = 0u;     // flags reset each launch
}

// ---------------- phase 1: xg[s*64+b][pcol] = x[b][s][:] @ Wp + bias ----------------
__global__ __launch_bounds__(256) void xproj_kernel(const float* __restrict__ x)
{
    __shared__ float As[8][132];   // [k][m], padded
    __shared__ float Bs[8][128];   // [k][n]
    int t  = threadIdx.x;
    int m0 = blockIdx.x * 128;
    int n0 = blockIdx.y * 128;
    int tm = t >> 4, tn = t & 15;

    int arow = t >> 1;
    int akq  = (t & 1) * 4;
    int gm = m0 + arow;
    int bb = gm & 63, ss = gm >> 6;
    const float* aptr = x + ((size_t)bb * SQ + ss) * HH + akq;

    int bkk = t >> 5;
    int bnq = (t & 31) * 4;
    const float* bptr = g_Wp + (size_t)bkk * GC + n0 + bnq;

    ull acc[8][4];
#pragma unroll
    for (int i = 0; i < 8; i++)
#pragma unroll
        for (int j = 0; j < 4; j++) acc[i][j] = 0ull;

    for (int k0 = 0; k0 < HH; k0 += 8) {
        float4 av = *(const float4*)(aptr + k0);
        float4 bv = *(const float4*)(bptr + (size_t)k0 * GC);
        __syncthreads();
        As[akq + 0][arow] = av.x;
        As[akq + 1][arow] = av.y;
        As[akq + 2][arow] = av.z;
        As[akq + 3][arow] = av.w;
        *(float4*)&Bs[bkk][bnq] = bv;
        __syncthreads();
#pragma unroll
        for (int kk = 0; kk < 8; kk++) {
            F4U2 b0, b1;
            float4 a0 = *(const float4*)&As[kk][tm * 8];
            float4 a1 = *(const float4*)&As[kk][tm * 8 + 4];
            b0.f4 = *(const float4*)&Bs[kk][tn * 8];
            b1.f4 = *(const float4*)&Bs[kk][tn * 8 + 4];
            ull bp_[4] = { b0.u2.x, b0.u2.y, b1.u2.x, b1.u2.y };
            float aa[8] = { a0.x, a0.y, a0.z, a0.w, a1.x, a1.y, a1.z, a1.w };
#pragma unroll
            for (int i = 0; i < 8; i++) {
                ull ad = pk2(aa[i], aa[i]);
#pragma unroll
                for (int j = 0; j < 4; j++) fma2(acc[i][j], ad, bp_[j]);
            }
        }
    }

    float4 bi0 = *(const float4*)(g_bp + n0 + tn * 8);
    float4 bi1 = *(const float4*)(g_bp + n0 + tn * 8 + 4);
#pragma unroll
    for (int i = 0; i < 8; i++) {
        float2 v0 = unpk(acc[i][0]), v1 = unpk(acc[i][1]);
        float2 v2 = unpk(acc[i][2]), v3 = unpk(acc[i][3]);
        float* o = g_xg + (size_t)(m0 + tm * 8 + i) * GC + n0 + tn * 8;
        float4 w0 = { v0.x + bi0.x, v0.y + bi0.y, v1.x + bi0.z, v1.y + bi0.w };
        float4 w1 = { v2.x + bi1.x, v2.y + bi1.y, v3.x + bi1.z, v3.y + bi1.w };
        *(float4*)o = w0;
        *(float4*)(o + 4) = w1;
    }
}

// ---------------- phase 2: persistent recurrence, warp-granular flag sync ----------------
// 128 CTAs = 16 groups (4 batches) x 8 col-CTAs (128 gate-cols = 32 units).
// Warp ks's k-slice [32ks,32ks+32) is produced entirely by CTA ks of the group:
// 1 lane polls that CTA's flag, the warp stages its slice, GEMM starts without
// any CTA-wide barrier. One __syncthreads per step (before the reduce).
__global__ __launch_bounds__(256, 1) void rnn_kernel()
{
    extern __shared__ float smU[];          // [256][128] = 128KB dynamic
    __shared__ ull  smH[8][32 * 4];         // [warp][kk*4 + b] duplicated pairs, 8KB
    __shared__ float smR[2][8][4][128];     // double-buffered partials, 32KB

    int t   = threadIdx.x;
    int grp = blockIdx.x >> 3;
    int r   = blockIdx.x & 7;
    int c0  = r * 128;

    int ks = t >> 5, ln = t & 31;           // warp / lane
    int eb = t >> 5, ecq = t & 31;          // epilogue map (t<128)
    int unit = r * 32 + ecq;

    // fill smU [k][128 cols]
    for (int q = t; q < HH * 32; q += 256) {
        int k = q >> 5, cq = q & 31;
        ((float4*)smU)[q] = *(const float4*)(g_Up + (size_t)k * GC + c0 + cq * 4);
    }
    __syncthreads();

    const unsigned* flag = &g_fl[grp][ks][0];
    float C = 0.0f;

    for (int s = 0; s < SQ; s++) {
        // prefetch xg before any blocking
        float4 xg4;
        if (t < 128)
            xg4 = __ldcs((const float4*)(g_xg + ((size_t)s * NB + grp * 4 + eb) * GC + c0 + 4 * ecq));

        // warp-granular wait on this warp's single producer CTA
        if (s > 0 && ln == 0) {
            unsigned tgt = (unsigned)s << 7;   // 128*s
            while (ldacq(flag) < tgt) { }
        }
        __syncwarp();
        {   // stage this warp's h slice (already duplicated pairs), warp-local
            const ulonglong2* src = (const ulonglong2*)&g_mb[s & 3][grp][ks * 32 + ln][0];
            ulonglong2 va = __ldcg(src);
            ulonglong2 vb = __ldcg(src + 1);
            *(ulonglong2*)&smH[ks][ln * 4]     = va;
            *(ulonglong2*)&smH[ks][ln * 4 + 2] = vb;
        }
        __syncwarp();

        // GEMM partials over this warp's 32-k slice
        ull a00 = 0, a01 = 0, a10 = 0, a11 = 0, a20 = 0, a21 = 0, a30 = 0, a31 = 0;
#pragma unroll
        for (int kk = 0; kk < 32; kk++) {
            F4U2 u; u.f4 = *(const float4*)&smU[(ks * 32 + kk) * 128 + 4 * ln];
            ulonglong2 hA = *(const ulonglong2*)&smH[ks][kk * 4];
            ulonglong2 hB = *(const ulonglong2*)&smH[ks][kk * 4 + 2];
            fma2(a00, hA.x, u.u2.x); fma2(a01, hA.x, u.u2.y);
            fma2(a10, hA.y, u.u2.x); fma2(a11, hA.y, u.u2.y);
            fma2(a20, hB.x, u.u2.x); fma2(a21, hB.x, u.u2.y);
            fma2(a30, hB.y, u.u2.x); fma2(a31, hB.y, u.u2.y);
        }
        {
            float* dst = &smR[s & 1][ks][0][4 * ln];
            float2 x0 = unpk(a00), x1 = unpk(a01);
            *(float4*)(dst + 0 * 128) = make_float4(x0.x, x0.y, x1.x, x1.y);
            x0 = unpk(a10); x1 = unpk(a11);
            *(float4*)(dst + 1 * 128) = make_float4(x0.x, x0.y, x1.x, x1.y);
            x0 = unpk(a20); x1 = unpk(a21);
            *(float4*)(dst + 2 * 128) = make_float4(x0.x, x0.y, x1.x, x1.y);
            x0 = unpk(a30); x1 = unpk(a31);
            *(float4*)(dst + 3 * 128) = make_float4(x0.x, x0.y, x1.x, x1.y);
        }
        __syncthreads();   // the one CTA barrier: all 8 partials ready

        // reduce + gates + state update + publish
        if (t < 128) {
            float4 g4 = xg4;
#pragma unroll
            for (int q = 0; q < 8; q++) {
                float4 pv = *(const float4*)&smR[s & 1][q][eb][4 * ecq];
                g4.x += pv.x; g4.y += pv.y; g4.z += pv.z; g4.w += pv.w;
            }
            float fg = fsig(g4.x), ig = fsig(g4.y), og = fsig(g4.z), cc = fsig(g4.w);
            C = fg * C + ig * cc;
            float h = og * ftanh(C);

            if (s < SQ - 1) {
                strel64(&g_mb[(s + 1) & 3][grp][unit][eb], pk2(h, h));
                redrel(&g_fl[grp][r][0]);   // release: orders the data store above
            } else {
                g_hT[(grp * 4 + eb) * HH + unit] = h;
            }
        }
    }
}

// ---------------- phase 3: out = h_T @ Why + bias_y ----------------
__global__ __launch_bounds__(256) void out_kernel(const float* __restrict__ Why,
                                                  const float* __restrict__ by,
                                                  float* __restrict__ out)
{
    __shared__ float hs[HH];
    int b = blockIdx.x, n = threadIdx.x;
    hs[n] = g_hT[b * HH + n];
    __syncthreads();
    float acc = by[n];
    for (int k = 0; k < HH; k++)
        acc = fmaf(hs[k], Why[(size_t)k * HH + n], acc);
    out[b * HH + n] = acc;
}

// ---------------- launch ----------------
extern "C" void kernel_launch(void* const* d_in, const int* in_sizes, int n_in,
                              void* d_out, int out_size)
{
    (void)in_sizes; (void)n_in; (void)out_size;
    const float* x   = (const float*)d_in[0];
    const float* Wf  = (const float*)d_in[1];
    const float* Uf  = (const float*)d_in[2];
    const float* bf  = (const float*)d_in[3];
    const float* Wi  = (const float*)d_in[4];
    const float* Ui  = (const float*)d_in[5];
    const float* bi  = (const float*)d_in[6];
    const float* Wc  = (const float*)d_in[7];
    const float* Uc  = (const float*)d_in[8];
    const float* bc  = (const float*)d_in[9];
    const float* Wo  = (const float*)d_in[10];
    const float* Uo  = (const float*)d_in[11];
    const float* bo  = (const float*)d_in[12];
    const float* Why = (const float*)d_in[13];
    const float* by  = (const float*)d_in[14];
    float* out = (float*)d_out;

    pack_kernel<<<1024, 256>>>(Wf, Uf, bf, Wi, Ui, bi, Wc, Uc, bc, Wo, Uo, bo);

    dim3 g1(2048, 8);
    xproj_kernel<<<g1, 256>>>(x);

    int smem = HH * 128 * (int)sizeof(float);   // 128KB dynamic (smU)
    cudaFuncSetAttribute(rnn_kernel, cudaFuncAttributeMaxDynamicSharedMemorySize, smem);
    rnn_kernel<<<128, 256, smem>>>();

    out_kernel<<<64, 256>>>(Why, by, out);
}